// round 12
// baseline (speedup 1.0000x reference)
#include <cuda_runtime.h>
#include <cuda_bf16.h>
#include <math.h>
#include <stdint.h>

// Problem constants
#define BB   2
#define HH   16
#define MM   2048
#define NN   2048
#define DD   2048
#define DH   128
#define DR   64
#define DCAT 192
// 1/sqrt(192) * log2(e): folded into Q projection so scores arrive in log2 domain
#define QSCALE_L2E 0.10411754f
#define EXP_SHIFT 8.0f

// -------------------- scratch --------------------
__device__ float g_Qcat[(long long)BB*HH*MM*DCAT];   // (B,H,M,192) pre-scaled by QSCALE_L2E
__device__ float g_Kcat[(long long)BB*HH*NN*DCAT];   // (B,H,N,192)
__device__ float g_Vt [(long long)BB*HH*DH*NN];      // (B,H,128,N)
__device__ float g_Ctx[(long long)BB*MM*HH*DH];      // (B*M, 2048)
__device__ float g_cq [(long long)BB*MM*DD];
__device__ float g_ckv[(long long)BB*NN*DD];
__device__ float g_wq [(long long)(HH*DH + HH*DR)*DD];
__device__ float g_wkv[(long long)(HH*DH + HH*DR + HH*DH)*DD];
__device__ float g_wo [(long long)DD*HH*DH];
__device__ float2 g_rope[MM * 32];

// -------------------- helpers --------------------
__device__ __forceinline__ float tf32r(float x) {
    uint32_t u;
    asm("cvt.rna.tf32.f32 %0, %1;" : "=r"(u) : "f"(x));
    return __uint_as_float(u);
}
__device__ __forceinline__ float ex2f(float x) {
    float r;
    asm("ex2.approx.f32 %0, %1;" : "=f"(r) : "f"(x));
    return r;
}
__device__ __forceinline__ void cp16(void* smem, const void* g) {
    uint32_t s = (uint32_t)__cvta_generic_to_shared(smem);
    asm volatile("cp.async.cg.shared.global [%0], [%1], 16;" :: "r"(s), "l"(g));
}
#define CP_COMMIT() asm volatile("cp.async.commit_group;" ::: "memory")
#define CP_WAIT(n)  asm volatile("cp.async.wait_group %0;" :: "n"(n) : "memory")

__device__ __forceinline__ void mma_tf32(float acc[4],
        uint32_t a0, uint32_t a1, uint32_t a2, uint32_t a3,
        uint32_t b0, uint32_t b1) {
    asm volatile(
        "mma.sync.aligned.m16n8k8.row.col.f32.tf32.tf32.f32 "
        "{%0,%1,%2,%3},{%4,%5,%6,%7},{%8,%9},{%0,%1,%2,%3};"
        : "+f"(acc[0]), "+f"(acc[1]), "+f"(acc[2]), "+f"(acc[3])
        : "r"(a0), "r"(a1), "r"(a2), "r"(a3), "r"(b0), "r"(b1));
}

__device__ __forceinline__ void ldm_x4(uint32_t r[4], uint32_t saddr) {
    asm volatile("ldmatrix.sync.aligned.m8n8.x4.shared.b16 {%0,%1,%2,%3}, [%4];"
                 : "=r"(r[0]), "=r"(r[1]), "=r"(r[2]), "=r"(r[3]) : "r"(saddr));
}

// -------------------- rope table --------------------
__global__ void rope_table_kernel() {
    int idx = blockIdx.x * blockDim.x + threadIdx.x;
    int i = idx & 31;
    int m = idx >> 5;
    double freq = exp(-(double)i / 32.0 * log(1.0e6));
    double ang  = (double)m * freq;
    double s, c;
    sincos(ang, &s, &c);
    g_rope[idx] = make_float2((float)c, (float)s);
}

// -------------------- merged input conversion --------------------
struct ConvArgs {
    const float4* src[8];
    float4*       dst[8];
    int           n4[8];
};
__global__ void conv8_kernel(ConvArgs a) {
    int seg = blockIdx.y;
    int i = blockIdx.x * blockDim.x + threadIdx.x;
    if (i < a.n4[seg]) {
        float4 v = a.src[seg][i];
        v.x = tf32r(v.x); v.y = tf32r(v.y); v.z = tf32r(v.z); v.w = tf32r(v.w);
        a.dst[seg][i] = v;
    }
}

// -------------------- epilogue modes --------------------
enum { EPI_PLAIN = 0, EPI_Q = 1, EPI_KV = 2 };

template<int MODE, bool ROUND>
__device__ __forceinline__ void epi_store2(float* __restrict__ C, float* __restrict__ C2,
                                           int ldc, int r, int c, float v0, float v1) {
    if (MODE == EPI_PLAIN) {
        C[(long long)r * ldc + c]     = v0;
        C[(long long)r * ldc + c + 1] = v1;
        return;
    }
    if (MODE == EPI_Q) { v0 *= QSCALE_L2E; v1 *= QSCALE_L2E; }
    int b = r >> 11, sr = r & 2047;
    if (c < 2048) {
        int h = c >> 7, d = c & 127;
        float* p = C + ((long long)((b * HH + h) * (MODE == EPI_Q ? MM : NN) + sr)) * DCAT + d;
        p[0] = tf32r(v0); p[1] = tf32r(v1);
    } else if (c < 3072) {
        int c2 = c - 2048, h = c2 >> 6, d = c2 & 63;
        float2 cs = g_rope[sr * 32 + (d >> 1)];
        float o0 = v0 * cs.x - v1 * cs.y;
        float o1 = v1 * cs.x + v0 * cs.y;
        float* p = C + ((long long)((b * HH + h) * (MODE == EPI_Q ? MM : NN) + sr)) * DCAT + DH + d;
        p[0] = tf32r(o0); p[1] = tf32r(o1);
    } else {
        int c2 = c - 3072, h = c2 >> 7, d = c2 & 127;
        float* p = C2 + ((long long)((b * HH + h) * DH + d)) * NN + sr;
        p[0]  = tf32r(v0);
        p[NN] = tf32r(v1);
    }
}

// -------------------- tf32 mma.sync GEMM: C = A * B^T --------------------
// CTA tile 256x128, 8 warps (4m x 2n) of 64x64, BK=16, 2-stage cp.async,
// 3 CTAs/SM (6 warps/SMSP). Stride 20 floats -> conflict-free ldmatrix.
#define SMSTRIDE 20
#define A_STG_F  (256 * SMSTRIDE)              // 5120 floats
#define B_STG_F  (128 * SMSTRIDE)              // 2560 floats
#define STG_F    (A_STG_F + B_STG_F)           // 7680 floats
#define SMEM_BYTES (2 * STG_F * 4)             // 61440 B

template<int MODE, bool ROUND>
__global__ void __launch_bounds__(256, 3)
mma_gemm(const float* __restrict__ A, int lda,
         const float* __restrict__ Bm, int ldb,
         float* __restrict__ C, float* __restrict__ C2, int ldc, int K)
{
    extern __shared__ float sm[];
    const float* Ab = A  + (long long)blockIdx.y * 256 * lda;
    const float* Bb = Bm + (long long)blockIdx.x * 128 * ldb;

    const int t = threadIdx.x;
    const int lane = t & 31;
    const int warp = t >> 5;           // 0..7
    const int wm = (warp & 3) * 64;    // 0,64,128,192
    const int wn = (warp >> 2) * 64;   // 0,64

    const int lrow = lane & 7;
    const int lsel = lane >> 3;
    const int a_row = lrow + (lsel & 1) * 8;
    const int a_col = (lsel >> 1) * 4;
    const int b_row = lrow + (lsel >> 1) * 8;
    const int b_col = (lsel & 1) * 4;

    const uint32_t smem0 = (uint32_t)__cvta_generic_to_shared(sm);

    float acc[4][8][4];
    #pragma unroll
    for (int i = 0; i < 4; i++)
        #pragma unroll
        for (int j = 0; j < 8; j++)
            #pragma unroll
            for (int q = 0; q < 4; q++) acc[i][j][q] = 0.f;

    const int KT = K >> 4;

    auto issue = [&](int kt, int buf) {
        float* Asb = sm + buf * STG_F;
        float* Bsb = Asb + A_STG_F;
        const float* Ag = Ab + kt * 16;
        const float* Bg = Bb + kt * 16;
        #pragma unroll
        for (int i = 0; i < 4; i++) {          // A: 256 rows x 16 cols
            int id = t + 256 * i;
            int row = id >> 2, cc = (id & 3) * 4;
            cp16(&Asb[row * SMSTRIDE + cc], Ag + (long long)row * lda + cc);
        }
        #pragma unroll
        for (int i = 0; i < 2; i++) {          // B: 128 rows x 16 cols
            int id = t + 256 * i;
            int row = id >> 2, cc = (id & 3) * 4;
            cp16(&Bsb[row * SMSTRIDE + cc], Bg + (long long)row * ldb + cc);
        }
        CP_COMMIT();
    };

    issue(0, 0);

    for (int kt = 0; kt < KT; kt++) {
        if (kt + 1 < KT) { issue(kt + 1, (kt + 1) & 1); CP_WAIT(1); }
        else             { CP_WAIT(0); }
        __syncthreads();

        uint32_t Asb = smem0 + ((kt & 1) * STG_F) * 4;
        uint32_t Bsb = Asb + A_STG_F * 4;

        #pragma unroll
        for (int ks = 0; ks < 2; ks++) {
            const int k0 = ks * 8;
            uint32_t af[4][4], bf[4][4];
            #pragma unroll
            for (int mi = 0; mi < 4; mi++)
                ldm_x4(af[mi], Asb + ((wm + mi * 16 + a_row) * SMSTRIDE + k0 + a_col) * 4);
            #pragma unroll
            for (int nj = 0; nj < 4; nj++)
                ldm_x4(bf[nj], Bsb + ((wn + nj * 16 + b_row) * SMSTRIDE + k0 + b_col) * 4);
            #pragma unroll
            for (int mi = 0; mi < 4; mi++)
                #pragma unroll
                for (int nj = 0; nj < 4; nj++) {
                    mma_tf32(acc[mi][2 * nj],     af[mi][0], af[mi][1], af[mi][2], af[mi][3],
                             bf[nj][0], bf[nj][1]);
                    mma_tf32(acc[mi][2 * nj + 1], af[mi][0], af[mi][1], af[mi][2], af[mi][3],
                             bf[nj][2], bf[nj][3]);
                }
        }
        __syncthreads();
    }

    const int fr = lane >> 2;
    const int fc = lane & 3;
    const int rowBase = blockIdx.y * 256 + wm;
    const int colBase = blockIdx.x * 128 + wn;
    #pragma unroll
    for (int mi = 0; mi < 4; mi++) {
        int r0 = rowBase + mi * 16 + fr;
        #pragma unroll
        for (int ni = 0; ni < 8; ni++) {
            int c0 = colBase + ni * 8 + fc * 2;
            epi_store2<MODE, ROUND>(C, C2, ldc, r0,     c0, acc[mi][ni][0], acc[mi][ni][1]);
            epi_store2<MODE, ROUND>(C, C2, ldc, r0 + 8, c0, acc[mi][ni][2], acc[mi][ni][3]);
        }
    }
}

// -------------------- fused flash attention (unchanged from round 10) ------
#define FQ_STRIDE 196
#define FK_STRIDE 36
#define FV_STRIDE 132
#define FQ_F (128 * FQ_STRIDE)
#define FK_F (128 * FK_STRIDE)
#define FL_SMEM_BYTES ((FQ_F + 3 * FK_F + 128 * FV_STRIDE) * 4)   // 223232 B

__global__ void __launch_bounds__(256)
flash_kernel(const float* __restrict__ Q, const float* __restrict__ Kc,
             const float* __restrict__ Vt, float* __restrict__ Ctx)
{
    extern __shared__ float sm[];
    float* Qs = sm;
    float* Ks = sm + FQ_F;                 // 3 buffers
    float* Vs = sm + FQ_F + 3 * FK_F;

    const int bh = blockIdx.y;
    const int m0 = blockIdx.x * 128;
    const int t = threadIdx.x;
    const int lane = t & 31;
    const int warp = t >> 5;
    const int fr = lane >> 2;
    const int fc = lane & 3;
    const int rw = warp * 16;

    const int lrow = lane & 7;
    const int lsel = lane >> 3;
    const int a_row = lrow + (lsel & 1) * 8;
    const int a_col = (lsel >> 1) * 4;
    const int b_row = lrow + (lsel >> 1) * 8;
    const int b_col = (lsel & 1) * 4;

    const uint32_t qs_b = (uint32_t)__cvta_generic_to_shared(Qs);
    const uint32_t ks_b = (uint32_t)__cvta_generic_to_shared(Ks);
    const uint32_t vs_b = (uint32_t)__cvta_generic_to_shared(Vs);

    const float* Qg = Q  + ((long long)bh * MM + m0) * DCAT;
    const float* Kg = Kc + (long long)bh * NN * DCAT;
    const float* Vg = Vt + (long long)bh * DH * NN;

    auto issueK = [&](int n0, int ksub, int buf) {
        float* dst = Ks + buf * FK_F;
        #pragma unroll
        for (int i = 0; i < 4; i++) {
            int id = t + 256 * i;
            int r = id >> 3, c = (id & 7) * 4;
            cp16(&dst[r * FK_STRIDE + c],
                 Kg + (long long)(n0 + r) * DCAT + ksub * 32 + c);
        }
    };
    auto issueV = [&](int n0) {
        #pragma unroll
        for (int i = 0; i < 16; i++) {
            int id = t + 256 * i;
            int r = id >> 5, c = (id & 31) * 4;
            cp16(&Vs[r * FV_STRIDE + c], Vg + (long long)r * NN + n0 + c);
        }
    };

    // Q load (own group)
    #pragma unroll
    for (int i = 0; i < 24; i++) {
        int id = t + 256 * i;
        int r = id / 48, c = (id % 48) * 4;
        cp16(&Qs[r * FQ_STRIDE + c], Qg + (long long)r * DCAT + c);
    }
    CP_COMMIT();

    // pipeline prologue: {K0}, {V + K1}
    issueK(0, 0, 0); CP_COMMIT();
    issueV(0); issueK(0, 1, 1); CP_COMMIT();

    float sacc[16][4], oacc[16][4];
    float lrun[2] = { 0.f, 0.f };
    #pragma unroll
    for (int i = 0; i < 16; i++)
        #pragma unroll
        for (int q = 0; q < 4; q++) oacc[i][q] = 0.f;

    for (int chunk = 0; chunk < 16; chunk++) {
        const int n0 = chunk * 128;
        #pragma unroll
        for (int i = 0; i < 16; i++)
            #pragma unroll
            for (int q = 0; q < 4; q++) sacc[i][q] = 0.f;

        for (int ksub = 0; ksub < 6; ksub++) {
            if (chunk == 15 && ksub == 5) { CP_WAIT(0); } else { CP_WAIT(1); }
            __syncthreads();
            uint32_t Kb = ks_b + ((ksub % 3) * FK_F) * 4;
            #pragma unroll
            for (int kk = 0; kk < 4; kk++) {
                int qc = ksub * 32 + kk * 8;
                uint32_t af[4];
                ldm_x4(af, qs_b + ((rw + a_row) * FQ_STRIDE + qc + a_col) * 4);
                #pragma unroll
                for (int np = 0; np < 8; np++) {
                    uint32_t bf[4];
                    ldm_x4(bf, Kb + ((16 * np + b_row) * FK_STRIDE + kk * 8 + b_col) * 4);
                    mma_tf32(sacc[2 * np],     af[0], af[1], af[2], af[3], bf[0], bf[1]);
                    mma_tf32(sacc[2 * np + 1], af[0], af[1], af[2], af[3], bf[2], bf[3]);
                }
            }
            if (ksub < 4) {
                issueK(n0, ksub + 2, (ksub + 2) % 3); CP_COMMIT();
            } else if (ksub == 4 && chunk < 15) {
                issueK(n0 + 128, 0, 0); CP_COMMIT();
            }
        }

        // static-shift softmax: p = exp2(s - 8)
        {
            float r0 = 0.f, r1 = 0.f;
            #pragma unroll
            for (int ni = 0; ni < 16; ni++) {
                float p0 = ex2f(sacc[ni][0] - EXP_SHIFT);
                float p1 = ex2f(sacc[ni][1] - EXP_SHIFT);
                float p2 = ex2f(sacc[ni][2] - EXP_SHIFT);
                float p3 = ex2f(sacc[ni][3] - EXP_SHIFT);
                r0 += p0 + p1;
                r1 += p2 + p3;
                sacc[ni][0] = tf32r(p0);
                sacc[ni][1] = tf32r(p1);
                sacc[ni][2] = tf32r(p2);
                sacc[ni][3] = tf32r(p3);
            }
            r0 += __shfl_xor_sync(0xFFFFFFFF, r0, 1);
            r0 += __shfl_xor_sync(0xFFFFFFFF, r0, 2);
            r1 += __shfl_xor_sync(0xFFFFFFFF, r1, 1);
            r1 += __shfl_xor_sync(0xFFFFFFFF, r1, 2);
            lrun[0] += r0;
            lrun[1] += r1;
        }

        // O += P @ V
        #pragma unroll
        for (int s = 0; s < 16; s++) {
            int srcA = (fr << 2) | (fc >> 1);
            int srcB = srcA + 2;
            float x0 = __shfl_sync(0xFFFFFFFF, sacc[s][0], srcA);
            float x1 = __shfl_sync(0xFFFFFFFF, sacc[s][1], srcA);
            float y0 = __shfl_sync(0xFFFFFFFF, sacc[s][0], srcB);
            float y1 = __shfl_sync(0xFFFFFFFF, sacc[s][1], srcB);
            float z0 = __shfl_sync(0xFFFFFFFF, sacc[s][2], srcA);
            float z1 = __shfl_sync(0xFFFFFFFF, sacc[s][3], srcA);
            float w0 = __shfl_sync(0xFFFFFFFF, sacc[s][2], srcB);
            float w1 = __shfl_sync(0xFFFFFFFF, sacc[s][3], srcB);
            bool odd = (fc & 1);
            uint32_t a0 = __float_as_uint(odd ? x1 : x0);
            uint32_t a2 = __float_as_uint(odd ? y1 : y0);
            uint32_t a1 = __float_as_uint(odd ? z1 : z0);
            uint32_t a3 = __float_as_uint(odd ? w1 : w0);
            #pragma unroll
            for (int np = 0; np < 8; np++) {
                uint32_t bf[4];
                ldm_x4(bf, vs_b + ((16 * np + b_row) * FV_STRIDE + 8 * s + b_col) * 4);
                mma_tf32(oacc[2 * np],     a0, a1, a2, a3, bf[0], bf[1]);
                mma_tf32(oacc[2 * np + 1], a0, a1, a2, a3, bf[2], bf[3]);
            }
        }
        __syncthreads();
        if (chunk < 15) {
            issueV(n0 + 128);
            issueK(n0 + 128, 1, 1);
            CP_COMMIT();
        }
    }

    const int b  = bh >> 4;
    const int hd = bh & 15;
    float inv0 = 1.f / lrun[0];
    float inv1 = 1.f / lrun[1];
    int r0 = m0 + rw + fr;
    #pragma unroll
    for (int nj = 0; nj < 16; nj++) {
        int d = hd * DH + nj * 8 + 2 * fc;
        long long base0 = ((long long)(b * MM + r0)) * (HH * DH) + d;
        long long base1 = ((long long)(b * MM + r0 + 8)) * (HH * DH) + d;
        Ctx[base0]     = tf32r(oacc[nj][0] * inv0);
        Ctx[base0 + 1] = tf32r(oacc[nj][1] * inv0);
        Ctx[base1]     = tf32r(oacc[nj][2] * inv1);
        Ctx[base1 + 1] = tf32r(oacc[nj][3] * inv1);
    }
}

// -------------------- launch --------------------
extern "C" void kernel_launch(void* const* d_in, const int* in_sizes, int n_in,
                              void* d_out, int out_size) {
    const float* query = (const float*)d_in[0];
    const float* kv    = (const float*)d_in[1];
    const float* W_QC  = (const float*)d_in[2];
    const float* W_KC  = (const float*)d_in[3];
    const float* W_QR  = (const float*)d_in[4];
    const float* W_KR  = (const float*)d_in[5];
    const float* W_V   = (const float*)d_in[6];
    const float* W_O   = (const float*)d_in[7];
    float* out = (float*)d_out;

    float *Qcat, *Kcat, *Vt, *Ctx, *cq, *ckv, *wq, *wkv, *wo;
    cudaGetSymbolAddress((void**)&Qcat, g_Qcat);
    cudaGetSymbolAddress((void**)&Kcat, g_Kcat);
    cudaGetSymbolAddress((void**)&Vt,   g_Vt);
    cudaGetSymbolAddress((void**)&Ctx,  g_Ctx);
    cudaGetSymbolAddress((void**)&cq,   g_cq);
    cudaGetSymbolAddress((void**)&ckv,  g_ckv);
    cudaGetSymbolAddress((void**)&wq,   g_wq);
    cudaGetSymbolAddress((void**)&wkv,  g_wkv);
    cudaGetSymbolAddress((void**)&wo,   g_wo);

    cudaFuncSetAttribute(mma_gemm<EPI_Q,    true>,  cudaFuncAttributeMaxDynamicSharedMemorySize, SMEM_BYTES);
    cudaFuncSetAttribute(mma_gemm<EPI_KV,   true>,  cudaFuncAttributeMaxDynamicSharedMemorySize, SMEM_BYTES);
    cudaFuncSetAttribute(mma_gemm<EPI_PLAIN,false>, cudaFuncAttributeMaxDynamicSharedMemorySize, SMEM_BYTES);
    cudaFuncSetAttribute(flash_kernel, cudaFuncAttributeMaxDynamicSharedMemorySize, FL_SMEM_BYTES);

    rope_table_kernel<<<(MM * 32) / 256, 256>>>();

    ConvArgs ca;
    ca.src[0] = (const float4*)query; ca.dst[0] = (float4*)cq;   ca.n4[0] = BB*MM*DD/4;
    ca.src[1] = (const float4*)kv;    ca.dst[1] = (float4*)ckv;  ca.n4[1] = BB*NN*DD/4;
    ca.src[2] = (const float4*)W_QC;  ca.dst[2] = (float4*)wq;                          ca.n4[2] = HH*DH*DD/4;
    ca.src[3] = (const float4*)W_QR;  ca.dst[3] = (float4*)(wq + (long long)HH*DH*DD);  ca.n4[3] = HH*DR*DD/4;
    ca.src[4] = (const float4*)W_KC;  ca.dst[4] = (float4*)wkv;                         ca.n4[4] = HH*DH*DD/4;
    ca.src[5] = (const float4*)W_KR;  ca.dst[5] = (float4*)(wkv + (long long)HH*DH*DD); ca.n4[5] = HH*DR*DD/4;
    ca.src[6] = (const float4*)W_V;   ca.dst[6] = (float4*)(wkv + (long long)(HH*DH + HH*DR)*DD); ca.n4[6] = HH*DH*DD/4;
    ca.src[7] = (const float4*)W_O;   ca.dst[7] = (float4*)wo;   ca.n4[7] = DD*HH*DH/4;
    {
        int maxn4 = BB*MM*DD/4;
        conv8_kernel<<<dim3((maxn4 + 255) / 256, 8), 256>>>(ca);
    }

    dim3 gblk(256);

    // merged projections: rows in 256-blocks
    mma_gemm<EPI_Q, true><<<dim3(3072 / 128, (BB * MM) / 256), gblk, SMEM_BYTES>>>(
        cq, DD, wq, DD, Qcat, nullptr, 0, DD);
    mma_gemm<EPI_KV, true><<<dim3(5120 / 128, (BB * NN) / 256), gblk, SMEM_BYTES>>>(
        ckv, DD, wkv, DD, Kcat, Vt, 0, DD);

    flash_kernel<<<dim3(MM / 128, BB * HH), 256, FL_SMEM_BYTES>>>(Qcat, Kcat, Vt, Ctx);

    mma_gemm<EPI_PLAIN, false><<<dim3(DD / 128, (BB * MM) / 256), gblk, SMEM_BYTES>>>(
        Ctx, HH * DH, wo, DD, out, nullptr, DD, HH * DH);
}

// round 14
// speedup vs baseline: 5.0416x; 5.0416x over previous
#include <cuda_runtime.h>
#include <cuda_bf16.h>
#include <math.h>
#include <stdint.h>

// Problem constants
#define BB   2
#define HH   16
#define MM   2048
#define NN   2048
#define DD   2048
#define DH   128
#define DR   64
#define DCAT 192
// 1/sqrt(192) * log2(e): folded into Q projection so scores arrive in log2 domain
#define QSCALE_L2E 0.10411754f
#define EXP_SHIFT 8.0f

// -------------------- scratch --------------------
__device__ float g_Qcat[(long long)BB*HH*MM*DCAT];   // (B,H,M,192) pre-scaled by QSCALE_L2E
__device__ float g_Kcat[(long long)BB*HH*NN*DCAT];   // (B,H,N,192)
__device__ float g_Vt [(long long)BB*HH*DH*NN];      // (B,H,128,N)
__device__ float g_Ctx[(long long)BB*MM*HH*DH];      // (B*M, 2048)
__device__ float g_cq [(long long)BB*MM*DD];
__device__ float g_ckv[(long long)BB*NN*DD];
__device__ float g_wq [(long long)(HH*DH + HH*DR)*DD];
__device__ float g_wkv[(long long)(HH*DH + HH*DR + HH*DH)*DD];
__device__ float g_wo [(long long)DD*HH*DH];
__device__ float2 g_rope[MM * 32];

// -------------------- helpers --------------------
__device__ __forceinline__ float tf32r(float x) {
    uint32_t u;
    asm("cvt.rna.tf32.f32 %0, %1;" : "=r"(u) : "f"(x));
    return __uint_as_float(u);
}
__device__ __forceinline__ float ex2f(float x) {
    float r;
    asm("ex2.approx.f32 %0, %1;" : "=f"(r) : "f"(x));
    return r;
}
__device__ __forceinline__ void cp16(void* smem, const void* g) {
    uint32_t s = (uint32_t)__cvta_generic_to_shared(smem);
    asm volatile("cp.async.cg.shared.global [%0], [%1], 16;" :: "r"(s), "l"(g));
}
#define CP_COMMIT() asm volatile("cp.async.commit_group;" ::: "memory")
#define CP_WAIT(n)  asm volatile("cp.async.wait_group %0;" :: "n"(n) : "memory")

__device__ __forceinline__ void mma_tf32(float acc[4],
        uint32_t a0, uint32_t a1, uint32_t a2, uint32_t a3,
        uint32_t b0, uint32_t b1) {
    asm volatile(
        "mma.sync.aligned.m16n8k8.row.col.f32.tf32.tf32.f32 "
        "{%0,%1,%2,%3},{%4,%5,%6,%7},{%8,%9},{%0,%1,%2,%3};"
        : "+f"(acc[0]), "+f"(acc[1]), "+f"(acc[2]), "+f"(acc[3])
        : "r"(a0), "r"(a1), "r"(a2), "r"(a3), "r"(b0), "r"(b1));
}

__device__ __forceinline__ void ldm_x4(uint32_t r[4], uint32_t saddr) {
    asm volatile("ldmatrix.sync.aligned.m8n8.x4.shared.b16 {%0,%1,%2,%3}, [%4];"
                 : "=r"(r[0]), "=r"(r[1]), "=r"(r[2]), "=r"(r[3]) : "r"(saddr));
}

// -------------------- rope table --------------------
__global__ void rope_table_kernel() {
    int idx = blockIdx.x * blockDim.x + threadIdx.x;
    int i = idx & 31;
    int m = idx >> 5;
    double freq = exp(-(double)i / 32.0 * log(1.0e6));
    double ang  = (double)m * freq;
    double s, c;
    sincos(ang, &s, &c);
    g_rope[idx] = make_float2((float)c, (float)s);
}

// -------------------- merged input conversion --------------------
struct ConvArgs {
    const float4* src[8];
    float4*       dst[8];
    int           n4[8];
};
__global__ void conv8_kernel(ConvArgs a) {
    int seg = blockIdx.y;
    int i = blockIdx.x * blockDim.x + threadIdx.x;
    if (i < a.n4[seg]) {
        float4 v = a.src[seg][i];
        v.x = tf32r(v.x); v.y = tf32r(v.y); v.z = tf32r(v.z); v.w = tf32r(v.w);
        a.dst[seg][i] = v;
    }
}

// -------------------- epilogue helpers --------------------
enum { EPI_PLAIN = 0, EPI_Q = 1, EPI_KV = 2 };

template<int MODE>
__device__ __forceinline__ void epi_store2(float* __restrict__ C, float* __restrict__ C2,
                                           int ldc, int r, int c, float v0, float v1) {
    if (MODE == EPI_PLAIN) {
        C[(long long)r * ldc + c]     = v0;
        C[(long long)r * ldc + c + 1] = v1;
        return;
    }
    if (MODE == EPI_Q) { v0 *= QSCALE_L2E; v1 *= QSCALE_L2E; }
    int b = r >> 11, sr = r & 2047;
    if (c < 2048) {
        int h = c >> 7, d = c & 127;
        float* p = C + ((long long)((b * HH + h) * 2048 + sr)) * DCAT + d;
        p[0] = tf32r(v0); p[1] = tf32r(v1);
    } else if (c < 3072) {
        int c2 = c - 2048, h = c2 >> 6, d = c2 & 63;
        float2 cs = g_rope[sr * 32 + (d >> 1)];
        float o0 = v0 * cs.x - v1 * cs.y;
        float o1 = v1 * cs.x + v0 * cs.y;
        float* p = C + ((long long)((b * HH + h) * 2048 + sr)) * DCAT + DH + d;
        p[0] = tf32r(o0); p[1] = tf32r(o1);
    } else {   // EPI_KV only: V -> Vt[b,h,d,n]
        int c2 = c - 3072, h = c2 >> 7, d = c2 & 127;
        float* p = C2 + ((long long)((b * HH + h) * DH + d)) * NN + sr;
        p[0]  = tf32r(v0);
        p[NN] = tf32r(v1);
    }
}

// -------------------- tf32 mma.sync GEMM mainloop (macro-shared body) ------
// 128x128 CTA tile, 4 warps (2x2), warp tile 64x64, BK=32, double-buffered.
#define SMSTRIDE 36
#define STAGE_F  (128 * SMSTRIDE)
#define SMEM_BYTES (4 * STAGE_F * 4)        // 73728 B

// -------------------- merged Q + KV projection GEMM --------------------
// grid (64, 32): bx<40 -> KV path (A=ckv, B=wkv), bx>=40 -> Q path (A=cq, B=wq).
__global__ void __launch_bounds__(128, 3)
mma_gemm_qkv(const float* __restrict__ cq, const float* __restrict__ ckv,
             const float* __restrict__ wq, const float* __restrict__ wkv,
             float* __restrict__ Qcat, float* __restrict__ Kcat, float* __restrict__ Vt)
{
    extern __shared__ float sm[];
    const int bx = blockIdx.x;
    const bool isQ = (bx >= 40);
    const int cx = isQ ? (bx - 40) : bx;
    const float* Ab = (isQ ? cq : ckv) + (long long)blockIdx.y * 128 * DD;
    const float* Bb = (isQ ? wq : wkv) + (long long)cx * 128 * DD;

    const int t = threadIdx.x;
    const int lane = t & 31;
    const int warp = t >> 5;
    const int wm = (warp & 1) * 64;
    const int wn = (warp >> 1) * 64;

    const int lrow = lane & 7;
    const int lsel = lane >> 3;
    const int a_row = lrow + (lsel & 1) * 8;
    const int a_col = (lsel >> 1) * 4;
    const int b_row = lrow + (lsel >> 1) * 8;
    const int b_col = (lsel & 1) * 4;

    const uint32_t smem0 = (uint32_t)__cvta_generic_to_shared(sm);

    float acc[4][8][4];
    #pragma unroll
    for (int i = 0; i < 4; i++)
        #pragma unroll
        for (int j = 0; j < 8; j++)
            #pragma unroll
            for (int q = 0; q < 4; q++) acc[i][j][q] = 0.f;

    auto issue = [&](int kt, int buf) {
        float* Asb = sm + buf * 2 * STAGE_F;
        float* Bsb = Asb + STAGE_F;
        const float* Ag = Ab + kt * 32;
        const float* Bg = Bb + kt * 32;
        #pragma unroll
        for (int i = 0; i < 8; i++) {
            int id = t + 128 * i;
            int row = id >> 3, cc = (id & 7) * 4;
            cp16(&Asb[row * SMSTRIDE + cc], Ag + (long long)row * DD + cc);
            cp16(&Bsb[row * SMSTRIDE + cc], Bg + (long long)row * DD + cc);
        }
        CP_COMMIT();
    };

    issue(0, 0);

    const int KT = DD >> 5;   // 64
    for (int kt = 0; kt < KT; kt++) {
        if (kt + 1 < KT) { issue(kt + 1, (kt + 1) & 1); CP_WAIT(1); }
        else             { CP_WAIT(0); }
        __syncthreads();

        uint32_t Asb = smem0 + ((kt & 1) * 2 * STAGE_F) * 4;
        uint32_t Bsb = Asb + STAGE_F * 4;

        #pragma unroll
        for (int ks = 0; ks < 4; ks++) {
            const int k0 = ks * 8;
            uint32_t af[4][4], bf[4][4];
            #pragma unroll
            for (int mi = 0; mi < 4; mi++)
                ldm_x4(af[mi], Asb + ((wm + mi * 16 + a_row) * SMSTRIDE + k0 + a_col) * 4);
            #pragma unroll
            for (int nj = 0; nj < 4; nj++)
                ldm_x4(bf[nj], Bsb + ((wn + nj * 16 + b_row) * SMSTRIDE + k0 + b_col) * 4);
            #pragma unroll
            for (int mi = 0; mi < 4; mi++)
                #pragma unroll
                for (int nj = 0; nj < 4; nj++) {
                    mma_tf32(acc[mi][2 * nj],     af[mi][0], af[mi][1], af[mi][2], af[mi][3],
                             bf[nj][0], bf[nj][1]);
                    mma_tf32(acc[mi][2 * nj + 1], af[mi][0], af[mi][1], af[mi][2], af[mi][3],
                             bf[nj][2], bf[nj][3]);
                }
        }
        __syncthreads();
    }

    const int fr = lane >> 2;
    const int fc = lane & 3;
    const int rowBase = blockIdx.y * 128 + wm;
    const int colBase = cx * 128 + wn;
    #pragma unroll
    for (int mi = 0; mi < 4; mi++) {
        int r0 = rowBase + mi * 16 + fr;
        #pragma unroll
        for (int ni = 0; ni < 8; ni++) {
            int c0 = colBase + ni * 8 + fc * 2;
            if (isQ) {
                epi_store2<EPI_Q>(Qcat, nullptr, 0, r0,     c0, acc[mi][ni][0], acc[mi][ni][1]);
                epi_store2<EPI_Q>(Qcat, nullptr, 0, r0 + 8, c0, acc[mi][ni][2], acc[mi][ni][3]);
            } else {
                epi_store2<EPI_KV>(Kcat, Vt, 0, r0,     c0, acc[mi][ni][0], acc[mi][ni][1]);
                epi_store2<EPI_KV>(Kcat, Vt, 0, r0 + 8, c0, acc[mi][ni][2], acc[mi][ni][3]);
            }
        }
    }
}

// -------------------- plain GEMM (output projection) --------------------
__global__ void __launch_bounds__(128, 3)
mma_gemm_plain(const float* __restrict__ A, int lda,
               const float* __restrict__ Bm, int ldb,
               float* __restrict__ C, int ldc, int K)
{
    extern __shared__ float sm[];
    const float* Ab = A  + (long long)blockIdx.y * 128 * lda;
    const float* Bb = Bm + (long long)blockIdx.x * 128 * ldb;

    const int t = threadIdx.x;
    const int lane = t & 31;
    const int warp = t >> 5;
    const int wm = (warp & 1) * 64;
    const int wn = (warp >> 1) * 64;

    const int lrow = lane & 7;
    const int lsel = lane >> 3;
    const int a_row = lrow + (lsel & 1) * 8;
    const int a_col = (lsel >> 1) * 4;
    const int b_row = lrow + (lsel >> 1) * 8;
    const int b_col = (lsel & 1) * 4;

    const uint32_t smem0 = (uint32_t)__cvta_generic_to_shared(sm);

    float acc[4][8][4];
    #pragma unroll
    for (int i = 0; i < 4; i++)
        #pragma unroll
        for (int j = 0; j < 8; j++)
            #pragma unroll
            for (int q = 0; q < 4; q++) acc[i][j][q] = 0.f;

    const int KT = K >> 5;

    auto issue = [&](int kt, int buf) {
        float* Asb = sm + buf * 2 * STAGE_F;
        float* Bsb = Asb + STAGE_F;
        const float* Ag = Ab + kt * 32;
        const float* Bg = Bb + kt * 32;
        #pragma unroll
        for (int i = 0; i < 8; i++) {
            int id = t + 128 * i;
            int row = id >> 3, cc = (id & 7) * 4;
            cp16(&Asb[row * SMSTRIDE + cc], Ag + (long long)row * lda + cc);
            cp16(&Bsb[row * SMSTRIDE + cc], Bg + (long long)row * ldb + cc);
        }
        CP_COMMIT();
    };

    issue(0, 0);

    for (int kt = 0; kt < KT; kt++) {
        if (kt + 1 < KT) { issue(kt + 1, (kt + 1) & 1); CP_WAIT(1); }
        else             { CP_WAIT(0); }
        __syncthreads();

        uint32_t Asb = smem0 + ((kt & 1) * 2 * STAGE_F) * 4;
        uint32_t Bsb = Asb + STAGE_F * 4;

        #pragma unroll
        for (int ks = 0; ks < 4; ks++) {
            const int k0 = ks * 8;
            uint32_t af[4][4], bf[4][4];
            #pragma unroll
            for (int mi = 0; mi < 4; mi++)
                ldm_x4(af[mi], Asb + ((wm + mi * 16 + a_row) * SMSTRIDE + k0 + a_col) * 4);
            #pragma unroll
            for (int nj = 0; nj < 4; nj++)
                ldm_x4(bf[nj], Bsb + ((wn + nj * 16 + b_row) * SMSTRIDE + k0 + b_col) * 4);
            #pragma unroll
            for (int mi = 0; mi < 4; mi++)
                #pragma unroll
                for (int nj = 0; nj < 4; nj++) {
                    mma_tf32(acc[mi][2 * nj],     af[mi][0], af[mi][1], af[mi][2], af[mi][3],
                             bf[nj][0], bf[nj][1]);
                    mma_tf32(acc[mi][2 * nj + 1], af[mi][0], af[mi][1], af[mi][2], af[mi][3],
                             bf[nj][2], bf[nj][3]);
                }
        }
        __syncthreads();
    }

    const int fr = lane >> 2;
    const int fc = lane & 3;
    const int rowBase = blockIdx.y * 128 + wm;
    const int colBase = blockIdx.x * 128 + wn;
    #pragma unroll
    for (int mi = 0; mi < 4; mi++) {
        int r0 = rowBase + mi * 16 + fr;
        #pragma unroll
        for (int ni = 0; ni < 8; ni++) {
            int c0 = colBase + ni * 8 + fc * 2;
            epi_store2<EPI_PLAIN>(C, nullptr, ldc, r0,     c0, acc[mi][ni][0], acc[mi][ni][1]);
            epi_store2<EPI_PLAIN>(C, nullptr, ldc, r0 + 8, c0, acc[mi][ni][2], acc[mi][ni][3]);
        }
    }
}

// -------------------- fused flash attention (round-10 proven version) ------
#define FQ_STRIDE 196
#define FK_STRIDE 36
#define FV_STRIDE 132
#define FQ_F (128 * FQ_STRIDE)
#define FK_F (128 * FK_STRIDE)
#define FL_SMEM_BYTES ((FQ_F + 3 * FK_F + 128 * FV_STRIDE) * 4)   // 223232 B

__global__ void __launch_bounds__(256)
flash_kernel(const float* __restrict__ Q, const float* __restrict__ Kc,
             const float* __restrict__ Vt, float* __restrict__ Ctx)
{
    extern __shared__ float sm[];
    float* Qs = sm;
    float* Ks = sm + FQ_F;                 // 3 buffers
    float* Vs = sm + FQ_F + 3 * FK_F;

    const int bh = blockIdx.y;
    const int m0 = blockIdx.x * 128;
    const int t = threadIdx.x;
    const int lane = t & 31;
    const int warp = t >> 5;
    const int fr = lane >> 2;
    const int fc = lane & 3;
    const int rw = warp * 16;

    const int lrow = lane & 7;
    const int lsel = lane >> 3;
    const int a_row = lrow + (lsel & 1) * 8;
    const int a_col = (lsel >> 1) * 4;
    const int b_row = lrow + (lsel >> 1) * 8;
    const int b_col = (lsel & 1) * 4;

    const uint32_t qs_b = (uint32_t)__cvta_generic_to_shared(Qs);
    const uint32_t ks_b = (uint32_t)__cvta_generic_to_shared(Ks);
    const uint32_t vs_b = (uint32_t)__cvta_generic_to_shared(Vs);

    const float* Qg = Q  + ((long long)bh * MM + m0) * DCAT;
    const float* Kg = Kc + (long long)bh * NN * DCAT;
    const float* Vg = Vt + (long long)bh * DH * NN;

    auto issueK = [&](int n0, int ksub, int buf) {
        float* dst = Ks + buf * FK_F;
        #pragma unroll
        for (int i = 0; i < 4; i++) {
            int id = t + 256 * i;
            int r = id >> 3, c = (id & 7) * 4;
            cp16(&dst[r * FK_STRIDE + c],
                 Kg + (long long)(n0 + r) * DCAT + ksub * 32 + c);
        }
    };
    auto issueV = [&](int n0) {
        #pragma unroll
        for (int i = 0; i < 16; i++) {
            int id = t + 256 * i;
            int r = id >> 5, c = (id & 31) * 4;
            cp16(&Vs[r * FV_STRIDE + c], Vg + (long long)r * NN + n0 + c);
        }
    };

    // Q load (own group)
    #pragma unroll
    for (int i = 0; i < 24; i++) {
        int id = t + 256 * i;
        int r = id / 48, c = (id % 48) * 4;
        cp16(&Qs[r * FQ_STRIDE + c], Qg + (long long)r * DCAT + c);
    }
    CP_COMMIT();

    // pipeline prologue: {K0}, {V + K1}
    issueK(0, 0, 0); CP_COMMIT();
    issueV(0); issueK(0, 1, 1); CP_COMMIT();

    float sacc[16][4], oacc[16][4];
    float lrun[2] = { 0.f, 0.f };
    #pragma unroll
    for (int i = 0; i < 16; i++)
        #pragma unroll
        for (int q = 0; q < 4; q++) oacc[i][q] = 0.f;

    for (int chunk = 0; chunk < 16; chunk++) {
        const int n0 = chunk * 128;
        #pragma unroll
        for (int i = 0; i < 16; i++)
            #pragma unroll
            for (int q = 0; q < 4; q++) sacc[i][q] = 0.f;

        for (int ksub = 0; ksub < 6; ksub++) {
            if (chunk == 15 && ksub == 5) { CP_WAIT(0); } else { CP_WAIT(1); }
            __syncthreads();
            uint32_t Kb = ks_b + ((ksub % 3) * FK_F) * 4;
            #pragma unroll
            for (int kk = 0; kk < 4; kk++) {
                int qc = ksub * 32 + kk * 8;
                uint32_t af[4];
                ldm_x4(af, qs_b + ((rw + a_row) * FQ_STRIDE + qc + a_col) * 4);
                #pragma unroll
                for (int np = 0; np < 8; np++) {
                    uint32_t bf[4];
                    ldm_x4(bf, Kb + ((16 * np + b_row) * FK_STRIDE + kk * 8 + b_col) * 4);
                    mma_tf32(sacc[2 * np],     af[0], af[1], af[2], af[3], bf[0], bf[1]);
                    mma_tf32(sacc[2 * np + 1], af[0], af[1], af[2], af[3], bf[2], bf[3]);
                }
            }
            if (ksub < 4) {
                issueK(n0, ksub + 2, (ksub + 2) % 3); CP_COMMIT();
            } else if (ksub == 4 && chunk < 15) {
                issueK(n0 + 128, 0, 0); CP_COMMIT();
            }
        }

        // static-shift softmax: p = exp2(s - 8)
        {
            float r0 = 0.f, r1 = 0.f;
            #pragma unroll
            for (int ni = 0; ni < 16; ni++) {
                float p0 = ex2f(sacc[ni][0] - EXP_SHIFT);
                float p1 = ex2f(sacc[ni][1] - EXP_SHIFT);
                float p2 = ex2f(sacc[ni][2] - EXP_SHIFT);
                float p3 = ex2f(sacc[ni][3] - EXP_SHIFT);
                r0 += p0 + p1;
                r1 += p2 + p3;
                sacc[ni][0] = tf32r(p0);
                sacc[ni][1] = tf32r(p1);
                sacc[ni][2] = tf32r(p2);
                sacc[ni][3] = tf32r(p3);
            }
            r0 += __shfl_xor_sync(0xFFFFFFFF, r0, 1);
            r0 += __shfl_xor_sync(0xFFFFFFFF, r0, 2);
            r1 += __shfl_xor_sync(0xFFFFFFFF, r1, 1);
            r1 += __shfl_xor_sync(0xFFFFFFFF, r1, 2);
            lrun[0] += r0;
            lrun[1] += r1;
        }

        // O += P @ V
        #pragma unroll
        for (int s = 0; s < 16; s++) {
            int srcA = (fr << 2) | (fc >> 1);
            int srcB = srcA + 2;
            float x0 = __shfl_sync(0xFFFFFFFF, sacc[s][0], srcA);
            float x1 = __shfl_sync(0xFFFFFFFF, sacc[s][1], srcA);
            float y0 = __shfl_sync(0xFFFFFFFF, sacc[s][0], srcB);
            float y1 = __shfl_sync(0xFFFFFFFF, sacc[s][1], srcB);
            float z0 = __shfl_sync(0xFFFFFFFF, sacc[s][2], srcA);
            float z1 = __shfl_sync(0xFFFFFFFF, sacc[s][3], srcA);
            float w0 = __shfl_sync(0xFFFFFFFF, sacc[s][2], srcB);
            float w1 = __shfl_sync(0xFFFFFFFF, sacc[s][3], srcB);
            bool odd = (fc & 1);
            uint32_t a0 = __float_as_uint(odd ? x1 : x0);
            uint32_t a2 = __float_as_uint(odd ? y1 : y0);
            uint32_t a1 = __float_as_uint(odd ? z1 : z0);
            uint32_t a3 = __float_as_uint(odd ? w1 : w0);
            #pragma unroll
            for (int np = 0; np < 8; np++) {
                uint32_t bf[4];
                ldm_x4(bf, vs_b + ((16 * np + b_row) * FV_STRIDE + 8 * s + b_col) * 4);
                mma_tf32(oacc[2 * np],     a0, a1, a2, a3, bf[0], bf[1]);
                mma_tf32(oacc[2 * np + 1], a0, a1, a2, a3, bf[2], bf[3]);
            }
        }
        __syncthreads();
        if (chunk < 15) {
            issueV(n0 + 128);
            issueK(n0 + 128, 1, 1);
            CP_COMMIT();
        }
    }

    const int b  = bh >> 4;
    const int hd = bh & 15;
    float inv0 = 1.f / lrun[0];
    float inv1 = 1.f / lrun[1];
    int r0 = m0 + rw + fr;
    #pragma unroll
    for (int nj = 0; nj < 16; nj++) {
        int d = hd * DH + nj * 8 + 2 * fc;
        long long base0 = ((long long)(b * MM + r0)) * (HH * DH) + d;
        long long base1 = ((long long)(b * MM + r0 + 8)) * (HH * DH) + d;
        Ctx[base0]     = tf32r(oacc[nj][0] * inv0);
        Ctx[base0 + 1] = tf32r(oacc[nj][1] * inv0);
        Ctx[base1]     = tf32r(oacc[nj][2] * inv1);
        Ctx[base1 + 1] = tf32r(oacc[nj][3] * inv1);
    }
}

// -------------------- launch --------------------
extern "C" void kernel_launch(void* const* d_in, const int* in_sizes, int n_in,
                              void* d_out, int out_size) {
    const float* query = (const float*)d_in[0];
    const float* kv    = (const float*)d_in[1];
    const float* W_QC  = (const float*)d_in[2];
    const float* W_KC  = (const float*)d_in[3];
    const float* W_QR  = (const float*)d_in[4];
    const float* W_KR  = (const float*)d_in[5];
    const float* W_V   = (const float*)d_in[6];
    const float* W_O   = (const float*)d_in[7];
    float* out = (float*)d_out;

    float *Qcat, *Kcat, *Vt, *Ctx, *cq, *ckv, *wq, *wkv, *wo;
    cudaGetSymbolAddress((void**)&Qcat, g_Qcat);
    cudaGetSymbolAddress((void**)&Kcat, g_Kcat);
    cudaGetSymbolAddress((void**)&Vt,   g_Vt);
    cudaGetSymbolAddress((void**)&Ctx,  g_Ctx);
    cudaGetSymbolAddress((void**)&cq,   g_cq);
    cudaGetSymbolAddress((void**)&ckv,  g_ckv);
    cudaGetSymbolAddress((void**)&wq,   g_wq);
    cudaGetSymbolAddress((void**)&wkv,  g_wkv);
    cudaGetSymbolAddress((void**)&wo,   g_wo);

    cudaFuncSetAttribute(mma_gemm_qkv,   cudaFuncAttributeMaxDynamicSharedMemorySize, SMEM_BYTES);
    cudaFuncSetAttribute(mma_gemm_plain, cudaFuncAttributeMaxDynamicSharedMemorySize, SMEM_BYTES);
    cudaFuncSetAttribute(flash_kernel,   cudaFuncAttributeMaxDynamicSharedMemorySize, FL_SMEM_BYTES);

    rope_table_kernel<<<(MM * 32) / 256, 256>>>();

    ConvArgs ca;
    ca.src[0] = (const float4*)query; ca.dst[0] = (float4*)cq;   ca.n4[0] = BB*MM*DD/4;
    ca.src[1] = (const float4*)kv;    ca.dst[1] = (float4*)ckv;  ca.n4[1] = BB*NN*DD/4;
    ca.src[2] = (const float4*)W_QC;  ca.dst[2] = (float4*)wq;                          ca.n4[2] = HH*DH*DD/4;
    ca.src[3] = (const float4*)W_QR;  ca.dst[3] = (float4*)(wq + (long long)HH*DH*DD);  ca.n4[3] = HH*DR*DD/4;
    ca.src[4] = (const float4*)W_KC;  ca.dst[4] = (float4*)wkv;                         ca.n4[4] = HH*DH*DD/4;
    ca.src[5] = (const float4*)W_KR;  ca.dst[5] = (float4*)(wkv + (long long)HH*DH*DD); ca.n4[5] = HH*DR*DD/4;
    ca.src[6] = (const float4*)W_V;   ca.dst[6] = (float4*)(wkv + (long long)(HH*DH + HH*DR)*DD); ca.n4[6] = HH*DH*DD/4;
    ca.src[7] = (const float4*)W_O;   ca.dst[7] = (float4*)wo;   ca.n4[7] = DD*HH*DH/4;
    {
        int maxn4 = BB*MM*DD/4;
        conv8_kernel<<<dim3((maxn4 + 255) / 256, 8), 256>>>(ca);
    }

    // ---- merged Q + KV projections: one launch, 64x32 grid ----
    // bx 0..39 = KV cols (5120/128), bx 40..63 = Q cols (3072/128)
    mma_gemm_qkv<<<dim3(64, (BB * MM) / 128), 128, SMEM_BYTES>>>(
        cq, ckv, wq, wkv, Qcat, Kcat, Vt);

    // ---- fused flash attention ----
    flash_kernel<<<dim3(MM / 128, BB * HH), 256, FL_SMEM_BYTES>>>(Qcat, Kcat, Vt, Ctx);

    // ---- output projection ----
    mma_gemm_plain<<<dim3(DD / 128, (BB * MM) / 128), 128, SMEM_BYTES>>>(
        Ctx, HH * DH, wo, DD, out, DD, HH * DH);
}